// round 2
// baseline (speedup 1.0000x reference)
#include <cuda_runtime.h>
#include <cuda_fp16.h>
#include <cuda_bf16.h>
#include <math.h>

#define A_ANG 180
#define R_RHO 180
#define AR    32400
#define Hh    128
#define Ww    128
#define HW    16384
#define Nn    8
#define CI1   256
#define DIM   128
#define NC    1024   /* Nn*DIM */

// ---------------- static device scratch (no cudaMalloc allowed) ----------------
__device__ unsigned char g_seg[A_ANG * HW];
__device__ __half        g_ft[(size_t)HW * NC];            // conv1 out, [pixel][n*128+c] fp16
__device__ float         g_acc[(size_t)Nn * DIM * AR];     // DHT out [n][c][a][r]
__device__ float         g_y2 [(size_t)Nn * DIM * AR];     // conv2 out
__device__ float         g_w2t[1152 * 128];                // transposed weights [k][co]
__device__ float         g_w3t[1152 * 128];

// ---------------- packed f32x2 helpers ----------------
__device__ __forceinline__ unsigned long long ffma2(unsigned long long a,
                                                    unsigned long long b,
                                                    unsigned long long c) {
    unsigned long long d;
    asm("fma.rn.f32x2 %0, %1, %2, %3;" : "=l"(d) : "l"(a), "l"(b), "l"(c));
    return d;
}
__device__ __forceinline__ unsigned long long pk2(float lo, float hi) {
    unsigned long long d;
    asm("mov.b64 %0, {%1, %2};" : "=l"(d) : "f"(lo), "f"(hi));
    return d;
}
__device__ __forceinline__ void unpk2(unsigned long long v, float& lo, float& hi) {
    asm("mov.b64 {%0, %1}, %2;" : "=f"(lo), "=f"(hi) : "l"(v));
}

// ---------------- seg table: fp64, bit-matches numpy binning ----------------
__global__ void seg_kernel() {
    int a = blockIdx.x;
    int p = blockIdx.y * 256 + threadIdx.x;
    double irho = (double)((int)(sqrt((double)(Hh * Hh + Ww * Ww)) + 1.0)) / (double)(R_RHO - 1);
    double theta = (double)a * (3.141592653589793 / (double)A_ANG);
    double tc = cos(theta) / irho;
    double ts = sin(theta) / irho;
    int y = p >> 7, x = p & (Ww - 1);
    double val = __dadd_rn(__dmul_rn(tc, (double)(x - Ww / 2)),
                           __dmul_rn(ts, (double)(y - Hh / 2)));
    long long r = (long long)rint(val) + R_RHO / 2;   // rint = round-half-even = np.round
    if (r < 0) r = 0;
    if (r > R_RHO - 1) r = R_RHO - 1;
    g_seg[a * HW + p] = (unsigned char)r;
}

// ---------------- weight transpose: w[co][k] -> wt[k][co], k = ci*9+tap ----------------
__global__ void wt_kernel(const float* __restrict__ w, float* __restrict__ wt) {
    int e = blockIdx.x * 256 + threadIdx.x;
    if (e < 1152 * 128) {
        int co = e & 127;
        int k  = e >> 7;
        wt[e] = w[co * 1152 + k];
    }
}

// ---------------- conv1: 1x1 conv + BN + ReLU, GEMM 128co x 64px, K=256 ----------------
__global__ __launch_bounds__(256) void conv1_kernel(
    const float* __restrict__ x, const float* __restrict__ w,
    const float* __restrict__ b, const float* __restrict__ g,
    const float* __restrict__ be, const float* __restrict__ m,
    const float* __restrict__ v)
{
    __shared__ float As[8][128];
    __shared__ float Bs[8][64];
    __shared__ float sS[128], tS[128];
    int t = threadIdx.x;
    if (t < 128) {
        float sc = g[t] * rsqrtf(v[t] + 1e-5f);
        sS[t] = sc;
        tS[t] = (b[t] - m[t]) * sc + be[t];
    }
    int col0 = blockIdx.x * 64;
    int n  = col0 >> 14;
    int p0 = col0 & (HW - 1);

    float acc[8][4];
#pragma unroll
    for (int i = 0; i < 8; i++)
#pragma unroll
        for (int j = 0; j < 4; j++) acc[i][j] = 0.f;

    int a_kk = t & 7;
    int b_cc = t & 63;
    int b_kb = t >> 6;

    for (int k0 = 0; k0 < CI1; k0 += 8) {
        __syncthreads();
#pragma unroll
        for (int i = 0; i < 4; i++) {
            int co = (t >> 3) + 32 * i;
            As[a_kk][co] = w[co * CI1 + k0 + a_kk];
        }
#pragma unroll
        for (int i = 0; i < 2; i++) {
            int kk = b_kb + 4 * i;
            Bs[kk][b_cc] = x[(size_t)(n * CI1 + k0 + kk) * HW + p0 + b_cc];
        }
        __syncthreads();
#pragma unroll
        for (int kk = 0; kk < 8; kk++) {
            float av[8], bv[4];
#pragma unroll
            for (int i = 0; i < 8; i++) av[i] = As[kk][(t & 15) + 16 * i];
#pragma unroll
            for (int j = 0; j < 4; j++) bv[j] = Bs[kk][(t >> 4) + 16 * j];
#pragma unroll
            for (int i = 0; i < 8; i++)
#pragma unroll
                for (int j = 0; j < 4; j++) acc[i][j] += av[i] * bv[j];
        }
    }
#pragma unroll
    for (int i = 0; i < 8; i++) {
        int co = (t & 15) + 16 * i;
        float sc = sS[co], tt = tS[co];
#pragma unroll
        for (int j = 0; j < 4; j++) {
            int p = p0 + (t >> 4) + 16 * j;
            float yv = fmaxf(acc[i][j] * sc + tt, 0.f);
            g_ft[(size_t)p * NC + n * DIM + co] = __float2half_rn(yv);
        }
    }
}

// ---------------- DHT: block per (angle, n); run-length smem accumulation ----------------
__global__ __launch_bounds__(128) void dht_kernel() {
    extern __shared__ unsigned char smraw[];
    float* accS = (float*)smraw;                         // 180*129 floats
    unsigned char* segS = smraw + 180 * 129 * 4;         // 16384 bytes
    int a = blockIdx.x, ncg = blockIdx.y, t = threadIdx.x;

    for (int i = t; i < 180 * 129; i += 128) accS[i] = 0.f;
    {
        const int4* gs = (const int4*)(g_seg + a * HW);
        int4* ss = (int4*)segS;
        for (int i = t; i < HW / 16; i += 128) ss[i] = gs[i];
    }
    __syncthreads();

    float th = (float)a * 0.017453292519943295f;
    bool xinner = fabsf(cosf(th)) <= fabsf(sinf(th));    // scan dir w/ small bin step

    const __half* fcol = g_ft + ncg * DIM + t;
    float run = 0.f;
    int rprev = -1;

    for (int ii = 0; ii < HW; ii += 8) {
        float v[8]; int pp[8];
#pragma unroll
        for (int u = 0; u < 8; u++) {
            int idx = ii + u;
            int p = xinner ? idx : (((idx & 127) << 7) | (idx >> 7));
            pp[u] = p;
            v[u] = __half2float(__ldg(fcol + (size_t)p * NC));
        }
#pragma unroll
        for (int u = 0; u < 8; u++) {
            int r = segS[pp[u]];
            if (r == rprev) {
                run += v[u];
            } else {
                if (rprev >= 0) accS[rprev * 129 + t] += run;
                run = v[u];
                rprev = r;
            }
        }
    }
    if (rprev >= 0) accS[rprev * 129 + t] += run;
    __syncthreads();

    // coalesced writeout: [n=ncg][c=cc][a][r]
    for (int cc = 0; cc < 128; cc++) {
        float* dst = g_acc + (size_t)(ncg * DIM + cc) * AR + a * R_RHO;
        for (int rr = t; rr < R_RHO; rr += 128) dst[rr] = accS[rr * 129 + cc];
    }
}

// ---------------- conv3x3 + BN + ReLU: implicit GEMM, packed f32x2 ----------------
// tile: 128 co x 96 cols (48 pairs), one angle row; grid (2 r-tiles, 180 a, 8 n).
// r-tiles start at r0 = 0 and 84 (12-col overlap, identical values, benign).
__global__ __launch_bounds__(256, 2) void conv3_kernel(
    const float* __restrict__ src, const float* __restrict__ wt,
    const float* __restrict__ b,  const float* __restrict__ g,
    const float* __restrict__ be, const float* __restrict__ m,
    const float* __restrict__ v,  float* __restrict__ dst)
{
    __shared__ __align__(16) float Ws[8 * 9 * 128];   // [ci][tap][co]
    __shared__ __align__(16) float Bs[8 * 3 * 100];   // [ci][ar][q], q -> r = r0-1+q
    __shared__ float sS[128], tS[128];

    int t  = threadIdx.x;
    int r0 = blockIdx.x ? 84 : 0;
    int a  = blockIdx.y;
    int n  = blockIdx.z;
    if (t < 128) {
        float sc = g[t] * rsqrtf(v[t] + 1e-5f);
        sS[t] = sc;
        tS[t] = (b[t] - m[t]) * sc + be[t];
    }
    int co_grp = t >> 4;          // 0..15 -> 8 co each
    int pr_grp = t & 15;          // 0..15 -> 3 pairs each (stride 16)

    unsigned long long acc[8][3];
#pragma unroll
    for (int i = 0; i < 8; i++)
#pragma unroll
        for (int j = 0; j < 3; j++) acc[i][j] = 0ULL;

    const float* srcn = src + (size_t)n * DIM * AR;

#pragma unroll 1
    for (int c0 = 0; c0 < DIM; c0 += 8) {
        __syncthreads();
        {   // stage weights: contiguous slice, float4 coalesced
            const float4* wsrc = (const float4*)(wt + (size_t)c0 * 9 * 128);
            float4* wdst = (float4*)Ws;
#pragma unroll
            for (int i = 0; i < 9; i++) wdst[t + 256 * i] = wsrc[t + 256 * i];
        }
        // stage input rows a-1..a+1, cols r0-1..r0+96, zero-padded
        for (int e = t; e < 8 * 3 * 98; e += 256) {
            int ci  = e / (3 * 98);
            int rem = e - ci * (3 * 98);
            int ar  = rem / 98;
            int q   = rem - ar * 98;
            int as  = a + ar - 1;
            int rs  = r0 - 1 + q;
            float val = 0.f;
            if ((unsigned)as < 180u && (unsigned)rs < 180u)
                val = srcn[((size_t)(c0 + ci) * 180 + as) * 180 + rs];
            Bs[(ci * 3 + ar) * 100 + q] = val;
        }
        __syncthreads();

#pragma unroll 1
        for (int ci = 0; ci < 8; ci++) {
#pragma unroll
            for (int ky = 0; ky < 3; ky++) {
                const float* brow = Bs + (ci * 3 + ky) * 100;
#pragma unroll
                for (int kx = 0; kx < 3; kx++) {
                    int kidx = (ci * 9 + ky * 3 + kx) * 128 + co_grp * 8;
                    float4 wa = *(const float4*)(Ws + kidx);
                    float4 wb = *(const float4*)(Ws + kidx + 4);
                    unsigned long long a2[8];
                    a2[0] = pk2(wa.x, wa.x); a2[1] = pk2(wa.y, wa.y);
                    a2[2] = pk2(wa.z, wa.z); a2[3] = pk2(wa.w, wa.w);
                    a2[4] = pk2(wb.x, wb.x); a2[5] = pk2(wb.y, wb.y);
                    a2[6] = pk2(wb.z, wb.z); a2[7] = pk2(wb.w, wb.w);
                    unsigned long long b2[3];
#pragma unroll
                    for (int j = 0; j < 3; j++) {
                        int q0 = 2 * (pr_grp + 16 * j) + kx;
                        if (kx == 1) {                      // odd offset: two scalar LDS
                            b2[j] = pk2(brow[q0], brow[q0 + 1]);
                        } else {                            // even: aligned float2
                            float2 bb = *(const float2*)(brow + q0);
                            b2[j] = pk2(bb.x, bb.y);
                        }
                    }
#pragma unroll
                    for (int i = 0; i < 8; i++)
#pragma unroll
                        for (int j = 0; j < 3; j++)
                            acc[i][j] = ffma2(a2[i], b2[j], acc[i][j]);
                }
            }
        }
    }

    // epilogue: BN + ReLU, float2 stores
#pragma unroll
    for (int i = 0; i < 8; i++) {
        int co = co_grp * 8 + i;
        float sc = sS[co], tt = tS[co];
        float* drow = dst + ((size_t)(n * DIM + co) * 180 + a) * 180 + r0;
#pragma unroll
        for (int j = 0; j < 3; j++) {
            int col = 2 * (pr_grp + 16 * j);
            float lo, hi;
            unpk2(acc[i][j], lo, hi);
            float2 o;
            o.x = fmaxf(lo * sc + tt, 0.f);
            o.y = fmaxf(hi * sc + tt, 0.f);
            *(float2*)(drow + col) = o;
        }
    }
}

// ---------------- launch ----------------
extern "C" void kernel_launch(void* const* d_in, const int* in_sizes, int n_in,
                              void* d_out, int out_size) {
    const float* x   = (const float*)d_in[0];
    const float* w1  = (const float*)d_in[1];
    const float* b1  = (const float*)d_in[2];
    const float* g1  = (const float*)d_in[3];
    const float* be1 = (const float*)d_in[4];
    const float* m1  = (const float*)d_in[5];
    const float* v1  = (const float*)d_in[6];
    const float* w2  = (const float*)d_in[7];
    const float* b2  = (const float*)d_in[8];
    const float* g2  = (const float*)d_in[9];
    const float* be2 = (const float*)d_in[10];
    const float* m2  = (const float*)d_in[11];
    const float* v2  = (const float*)d_in[12];
    const float* w3  = (const float*)d_in[13];
    const float* b3  = (const float*)d_in[14];
    const float* g3  = (const float*)d_in[15];
    const float* be3 = (const float*)d_in[16];
    const float* m3  = (const float*)d_in[17];
    const float* v3  = (const float*)d_in[18];
    float* out = (float*)d_out;

    void *p_w2t, *p_w3t, *p_acc, *p_y2;
    cudaGetSymbolAddress(&p_w2t, g_w2t);
    cudaGetSymbolAddress(&p_w3t, g_w3t);
    cudaGetSymbolAddress(&p_acc, g_acc);
    cudaGetSymbolAddress(&p_y2,  g_y2);

    static int smem_set = 0;
    int dht_smem = 180 * 129 * 4 + HW;   // 109264 B
    if (!smem_set) {
        cudaFuncSetAttribute(dht_kernel, cudaFuncAttributeMaxDynamicSharedMemorySize, dht_smem);
        smem_set = 1;
    }

    seg_kernel<<<dim3(A_ANG, HW / 256), 256>>>();
    wt_kernel<<<(1152 * 128 + 255) / 256, 256>>>(w2, (float*)p_w2t);
    wt_kernel<<<(1152 * 128 + 255) / 256, 256>>>(w3, (float*)p_w3t);
    conv1_kernel<<<(Nn * HW) / 64, 256>>>(x, w1, b1, g1, be1, m1, v1);
    dht_kernel<<<dim3(A_ANG, Nn), 128, dht_smem>>>();
    conv3_kernel<<<dim3(2, A_ANG, Nn), 256>>>((const float*)p_acc, (const float*)p_w2t,
                                              b2, g2, be2, m2, v2, (float*)p_y2);
    conv3_kernel<<<dim3(2, A_ANG, Nn), 256>>>((const float*)p_y2, (const float*)p_w3t,
                                              b3, g3, be3, m3, v3, out);
}

// round 3
// speedup vs baseline: 1.1589x; 1.1589x over previous
#include <cuda_runtime.h>
#include <cuda_fp16.h>
#include <cuda_bf16.h>
#include <math.h>

#define A_ANG 180
#define R_RHO 180
#define AR    32400
#define Hh    128
#define Ww    128
#define HW    16384
#define Nn    8
#define CI1   256
#define DIM   128
#define NC    1024   /* Nn*DIM */

// ---------------- static device scratch (no cudaMalloc allowed) ----------------
__device__ unsigned char g_seg[A_ANG * HW];
__device__ __half        g_ft[(size_t)HW * NC];            // conv1 out, [pixel][n*128+c] fp16
__device__ float         g_acc[(size_t)Nn * DIM * AR];     // DHT out [n][c][a][r]
__device__ float         g_y2 [(size_t)Nn * DIM * AR];     // conv2 out
__device__ float         g_w2t[1152 * 128];                // transposed weights [k][co], tf32-rounded
__device__ float         g_w3t[1152 * 128];

__device__ __forceinline__ float to_tf32(float x) {
    float y;
    asm("cvt.rna.tf32.f32 %0, %1;" : "=f"(y) : "f"(x));
    return y;
}

// ---------------- seg table: fp64, bit-matches numpy binning ----------------
__global__ void seg_kernel() {
    int a = blockIdx.x;
    int p = blockIdx.y * 256 + threadIdx.x;
    double irho = (double)((int)(sqrt((double)(Hh * Hh + Ww * Ww)) + 1.0)) / (double)(R_RHO - 1);
    double theta = (double)a * (3.141592653589793 / (double)A_ANG);
    double tc = cos(theta) / irho;
    double ts = sin(theta) / irho;
    int y = p >> 7, x = p & (Ww - 1);
    double val = __dadd_rn(__dmul_rn(tc, (double)(x - Ww / 2)),
                           __dmul_rn(ts, (double)(y - Hh / 2)));
    long long r = (long long)rint(val) + R_RHO / 2;   // rint = round-half-even = np.round
    if (r < 0) r = 0;
    if (r > R_RHO - 1) r = R_RHO - 1;
    g_seg[a * HW + p] = (unsigned char)r;
}

// ---------------- weight transpose + tf32 round: w[co][k] -> wt[k][co] ----------------
__global__ void wt_kernel(const float* __restrict__ w, float* __restrict__ wt) {
    int e = blockIdx.x * 256 + threadIdx.x;
    if (e < 1152 * 128) {
        int co = e & 127;
        int k  = e >> 7;
        wt[e] = to_tf32(w[co * 1152 + k]);
    }
}

// ---------------- conv1: 1x1 conv + BN + ReLU, GEMM 128co x 64px, K=256 ----------------
__global__ __launch_bounds__(256) void conv1_kernel(
    const float* __restrict__ x, const float* __restrict__ w,
    const float* __restrict__ b, const float* __restrict__ g,
    const float* __restrict__ be, const float* __restrict__ m,
    const float* __restrict__ v)
{
    __shared__ float As[8][128];
    __shared__ float Bs[8][64];
    __shared__ float sS[128], tS[128];
    int t = threadIdx.x;
    if (t < 128) {
        float sc = g[t] * rsqrtf(v[t] + 1e-5f);
        sS[t] = sc;
        tS[t] = (b[t] - m[t]) * sc + be[t];
    }
    int col0 = blockIdx.x * 64;
    int n  = col0 >> 14;
    int p0 = col0 & (HW - 1);

    float acc[8][4];
#pragma unroll
    for (int i = 0; i < 8; i++)
#pragma unroll
        for (int j = 0; j < 4; j++) acc[i][j] = 0.f;

    int a_kk = t & 7;
    int b_cc = t & 63;
    int b_kb = t >> 6;

    for (int k0 = 0; k0 < CI1; k0 += 8) {
        __syncthreads();
#pragma unroll
        for (int i = 0; i < 4; i++) {
            int co = (t >> 3) + 32 * i;
            As[a_kk][co] = w[co * CI1 + k0 + a_kk];
        }
#pragma unroll
        for (int i = 0; i < 2; i++) {
            int kk = b_kb + 4 * i;
            Bs[kk][b_cc] = x[(size_t)(n * CI1 + k0 + kk) * HW + p0 + b_cc];
        }
        __syncthreads();
#pragma unroll
        for (int kk = 0; kk < 8; kk++) {
            float av[8], bv[4];
#pragma unroll
            for (int i = 0; i < 8; i++) av[i] = As[kk][(t & 15) + 16 * i];
#pragma unroll
            for (int j = 0; j < 4; j++) bv[j] = Bs[kk][(t >> 4) + 16 * j];
#pragma unroll
            for (int i = 0; i < 8; i++)
#pragma unroll
                for (int j = 0; j < 4; j++) acc[i][j] += av[i] * bv[j];
        }
    }
#pragma unroll
    for (int i = 0; i < 8; i++) {
        int co = (t & 15) + 16 * i;
        float sc = sS[co], tt = tS[co];
#pragma unroll
        for (int j = 0; j < 4; j++) {
            int p = p0 + (t >> 4) + 16 * j;
            float yv = fmaxf(acc[i][j] * sc + tt, 0.f);
            g_ft[(size_t)p * NC + n * DIM + co] = __float2half_rn(yv);
        }
    }
}

// ---------------- DHT: block per (angle, n); run-length smem accumulation ----------------
__global__ __launch_bounds__(128) void dht_kernel() {
    extern __shared__ unsigned char smraw[];
    float* accS = (float*)smraw;                         // 180*129 floats
    unsigned char* segS = smraw + 180 * 129 * 4;         // 16384 bytes
    int a = blockIdx.x, ncg = blockIdx.y, t = threadIdx.x;

    for (int i = t; i < 180 * 129; i += 128) accS[i] = 0.f;
    {
        const int4* gs = (const int4*)(g_seg + a * HW);
        int4* ss = (int4*)segS;
        for (int i = t; i < HW / 16; i += 128) ss[i] = gs[i];
    }
    __syncthreads();

    float th = (float)a * 0.017453292519943295f;
    bool xinner = fabsf(cosf(th)) <= fabsf(sinf(th));    // scan dir w/ small bin step

    const __half* fcol = g_ft + ncg * DIM + t;
    float run = 0.f;
    int rprev = -1;

    for (int ii = 0; ii < HW; ii += 8) {
        float v[8]; int pp[8];
#pragma unroll
        for (int u = 0; u < 8; u++) {
            int idx = ii + u;
            int p = xinner ? idx : (((idx & 127) << 7) | (idx >> 7));
            pp[u] = p;
            v[u] = __half2float(__ldg(fcol + (size_t)p * NC));
        }
#pragma unroll
        for (int u = 0; u < 8; u++) {
            int r = segS[pp[u]];
            if (r == rprev) {
                run += v[u];
            } else {
                if (rprev >= 0) accS[rprev * 129 + t] += run;
                run = v[u];
                rprev = r;
            }
        }
    }
    if (rprev >= 0) accS[rprev * 129 + t] += run;
    __syncthreads();

    for (int cc = 0; cc < 128; cc++) {
        float* dst = g_acc + (size_t)(ncg * DIM + cc) * AR + a * R_RHO;
        for (int rr = t; rr < R_RHO; rr += 128) dst[rr] = accS[rr * 129 + cc];
    }
}

// ---------------- conv3x3 + BN + ReLU: tf32 mma.sync implicit GEMM ----------------
// tile: 128 co x 96 cols (one angle row); grid (2 r-tiles @ r0=0/84, 180 a, 8 n).
// K = 1152 staged in ci-chunks of 8; taps outer so each mma reduces over ci(8).
// smem: Ws[tap][ci][co pad136] (bank-free A frags), Bs[ci s312][ar s104][98]
// (bank-free B frags), dynamic 50176 B.
#define WS_F   (9 * 8 * 136)      /* 9792 floats  */
#define BS_F   (8 * 312)          /* 2496 floats  */
#define C3_SMEM ((WS_F + BS_F + 256) * 4)

__global__ __launch_bounds__(256) void conv3_kernel(
    const float* __restrict__ src, const float* __restrict__ wt,
    const float* __restrict__ b,  const float* __restrict__ g,
    const float* __restrict__ be, const float* __restrict__ m,
    const float* __restrict__ v,  float* __restrict__ dst)
{
    extern __shared__ float dyn[];
    float* Ws  = dyn;                 // [tap*1088 + ci*136 + co]
    float* BsS = dyn + WS_F;          // [ci*312 + ar*104 + rr], rr -> r = r0-1+rr
    float* sS  = dyn + WS_F + BS_F;
    float* tS  = sS + 128;

    int t  = threadIdx.x;
    int r0 = blockIdx.x * 84;         // 0 or 84 (12-col overlap, identical values)
    int a  = blockIdx.y;
    int n  = blockIdx.z;
    if (t < 128) {
        float sc = g[t] * rsqrtf(v[t] + 1e-5f);
        sS[t] = sc;
        tS[t] = (b[t] - m[t]) * sc + be[t];
    }

    int lane = t & 31, warp = t >> 5;
    int grp = lane >> 2, q4 = lane & 3;
    int co_base = warp * 16;

    float acc[12][4];
#pragma unroll
    for (int j = 0; j < 12; j++)
#pragma unroll
        for (int i = 0; i < 4; i++) acc[j][i] = 0.f;

    const float* srcn = src + (size_t)n * DIM * AR;

#pragma unroll 1
    for (int c0 = 0; c0 < DIM; c0 += 8) {
        __syncthreads();
        // stage weights: Ws[tap][ci][co], source wt[(c0+ci)*9+tap][co] (coalesced in co)
        for (int e = t; e < 9 * 8 * 128; e += 256) {
            int tap = e >> 10;
            int ci  = (e >> 7) & 7;
            int co  = e & 127;
            Ws[tap * 1088 + ci * 136 + co] = wt[((size_t)(c0 + ci) * 9 + tap) * 128 + co];
        }
        // stage input rows a-1..a+1, cols r0-1..r0+96 (98 values), zero-padded, tf32-rounded
        for (int e = t; e < 8 * 3 * 98; e += 256) {
            int ci  = e / 294;
            int rem = e - ci * 294;
            int ar  = rem / 98;
            int qq  = rem - ar * 98;
            int as  = a + ar - 1;
            int rs  = r0 - 1 + qq;
            float val = 0.f;
            if ((unsigned)as < 180u && (unsigned)rs < 180u)
                val = srcn[((size_t)(c0 + ci) * 180 + as) * 180 + rs];
            BsS[ci * 312 + ar * 104 + qq] = to_tf32(val);
        }
        __syncthreads();

#pragma unroll
        for (int tap = 0; tap < 9; tap++) {
            int ky = tap / 3, kx = tap - 3 * (tap / 3);
            const float* wA = Ws + tap * 1088;
            // A frag (16x8, row=co, col=ci): a0(g,q4) a1(g+8,q4) a2(g,q4+4) a3(g+8,q4+4)
            unsigned av0 = __float_as_uint(wA[q4 * 136 + co_base + grp]);
            unsigned av1 = __float_as_uint(wA[q4 * 136 + co_base + grp + 8]);
            unsigned av2 = __float_as_uint(wA[(q4 + 4) * 136 + co_base + grp]);
            unsigned av3 = __float_as_uint(wA[(q4 + 4) * 136 + co_base + grp + 8]);
            const float* bB = BsS + ky * 104 + kx + grp;
#pragma unroll
            for (int jn = 0; jn < 12; jn++) {
                // B frag (8x8 col-major, row=ci, col=r): b0(q4, grp) b1(q4+4, grp)
                unsigned bv0 = __float_as_uint(bB[q4 * 312 + jn * 8]);
                unsigned bv1 = __float_as_uint(bB[(q4 + 4) * 312 + jn * 8]);
                asm volatile(
                    "mma.sync.aligned.m16n8k8.row.col.f32.tf32.tf32.f32 "
                    "{%0,%1,%2,%3}, {%4,%5,%6,%7}, {%8,%9}, {%0,%1,%2,%3};"
                    : "+f"(acc[jn][0]), "+f"(acc[jn][1]),
                      "+f"(acc[jn][2]), "+f"(acc[jn][3])
                    : "r"(av0), "r"(av1), "r"(av2), "r"(av3),
                      "r"(bv0), "r"(bv1));
            }
        }
    }

    // epilogue: BN + ReLU. D frag: c0/c1 at row grp, cols q4*2/q4*2+1; c2/c3 at row grp+8.
    int co0 = co_base + grp;
    int co1 = co0 + 8;
    float sc0 = sS[co0], tt0 = tS[co0];
    float sc1 = sS[co1], tt1 = tS[co1];
    float* d0 = dst + ((size_t)(n * DIM + co0) * 180 + a) * 180 + r0 + q4 * 2;
    float* d1 = dst + ((size_t)(n * DIM + co1) * 180 + a) * 180 + r0 + q4 * 2;
#pragma unroll
    for (int jn = 0; jn < 12; jn++) {
        float2 o0, o1;
        o0.x = fmaxf(acc[jn][0] * sc0 + tt0, 0.f);
        o0.y = fmaxf(acc[jn][1] * sc0 + tt0, 0.f);
        o1.x = fmaxf(acc[jn][2] * sc1 + tt1, 0.f);
        o1.y = fmaxf(acc[jn][3] * sc1 + tt1, 0.f);
        *(float2*)(d0 + jn * 8) = o0;
        *(float2*)(d1 + jn * 8) = o1;
    }
}

// ---------------- launch ----------------
extern "C" void kernel_launch(void* const* d_in, const int* in_sizes, int n_in,
                              void* d_out, int out_size) {
    const float* x   = (const float*)d_in[0];
    const float* w1  = (const float*)d_in[1];
    const float* b1  = (const float*)d_in[2];
    const float* g1  = (const float*)d_in[3];
    const float* be1 = (const float*)d_in[4];
    const float* m1  = (const float*)d_in[5];
    const float* v1  = (const float*)d_in[6];
    const float* w2  = (const float*)d_in[7];
    const float* b2  = (const float*)d_in[8];
    const float* g2  = (const float*)d_in[9];
    const float* be2 = (const float*)d_in[10];
    const float* m2  = (const float*)d_in[11];
    const float* v2  = (const float*)d_in[12];
    const float* w3  = (const float*)d_in[13];
    const float* b3  = (const float*)d_in[14];
    const float* g3  = (const float*)d_in[15];
    const float* be3 = (const float*)d_in[16];
    const float* m3  = (const float*)d_in[17];
    const float* v3  = (const float*)d_in[18];
    float* out = (float*)d_out;

    void *p_w2t, *p_w3t, *p_acc, *p_y2;
    cudaGetSymbolAddress(&p_w2t, g_w2t);
    cudaGetSymbolAddress(&p_w3t, g_w3t);
    cudaGetSymbolAddress(&p_acc, g_acc);
    cudaGetSymbolAddress(&p_y2,  g_y2);

    int dht_smem = 180 * 129 * 4 + HW;   // 109264 B
    cudaFuncSetAttribute(dht_kernel, cudaFuncAttributeMaxDynamicSharedMemorySize, dht_smem);
    cudaFuncSetAttribute(conv3_kernel, cudaFuncAttributeMaxDynamicSharedMemorySize, C3_SMEM);

    seg_kernel<<<dim3(A_ANG, HW / 256), 256>>>();
    wt_kernel<<<(1152 * 128 + 255) / 256, 256>>>(w2, (float*)p_w2t);
    wt_kernel<<<(1152 * 128 + 255) / 256, 256>>>(w3, (float*)p_w3t);
    conv1_kernel<<<(Nn * HW) / 64, 256>>>(x, w1, b1, g1, be1, m1, v1);
    dht_kernel<<<dim3(A_ANG, Nn), 128, dht_smem>>>();
    conv3_kernel<<<dim3(2, A_ANG, Nn), 256, C3_SMEM>>>((const float*)p_acc, (const float*)p_w2t,
                                                       b2, g2, be2, m2, v2, (float*)p_y2);
    conv3_kernel<<<dim3(2, A_ANG, Nn), 256, C3_SMEM>>>((const float*)p_y2, (const float*)p_w3t,
                                                       b3, g3, be3, m3, v3, out);
}

// round 5
// speedup vs baseline: 4.5410x; 3.9185x over previous
#include <cuda_runtime.h>
#include <cuda_fp16.h>
#include <cuda_bf16.h>
#include <math.h>
#include <stdint.h>

#define A_ANG 180
#define R_RHO 180
#define AR    32400
#define Hh    128
#define Ww    128
#define HW    16384
#define Nn    8
#define CI1   256
#define DIM   128
#define NC    1024   /* Nn*DIM */

// ---------------- static device scratch ----------------
__device__ unsigned char  g_seg[A_ANG * HW];
__device__ __half         g_ft[(size_t)HW * NC];           // conv1 out, [pixel][n*128+c] fp16
__device__ float          g_acc[(size_t)Nn * DIM * AR];    // DHT out, NCHW [n][c][a][r]
__device__ float          g_y2 [(size_t)Nn * DIM * AR];    // conv2 out
__device__ float          g_w2t[1152 * 128];               // weights [k][co], k=ci*9+tap, tf32
__device__ float          g_w3t[1152 * 128];
__device__ unsigned short g_csr_idx[A_ANG * HW];           // pixel lists per (angle, bin)
__device__ int            g_csr_ptr[A_ANG * 181];          // row pointers per angle

__device__ __forceinline__ float to_tf32(float x) {
    float y;
    asm("cvt.rna.tf32.f32 %0, %1;" : "=f"(y) : "f"(x));
    return y;
}

// ---------------- seg table: fp64, bit-matches numpy binning ----------------
__global__ void seg_kernel() {
    int a = blockIdx.x;
    int p = blockIdx.y * 256 + threadIdx.x;
    double irho = (double)((int)(sqrt((double)(Hh * Hh + Ww * Ww)) + 1.0)) / (double)(R_RHO - 1);
    double theta = (double)a * (3.141592653589793 / (double)A_ANG);
    double tc = cos(theta) / irho;
    double ts = sin(theta) / irho;
    int y = p >> 7, x = p & (Ww - 1);
    double val = __dadd_rn(__dmul_rn(tc, (double)(x - Ww / 2)),
                           __dmul_rn(ts, (double)(y - Hh / 2)));
    long long r = (long long)rint(val) + R_RHO / 2;
    if (r < 0) r = 0;
    if (r > R_RHO - 1) r = R_RHO - 1;
    g_seg[a * HW + p] = (unsigned char)r;
}

// ---------------- CSR build: per angle, deterministic two-pass rank fill ----------------
__global__ __launch_bounds__(128) void csr_kernel() {
    __shared__ unsigned short hist[128][180];   // [pixel-chunk][bin]
    __shared__ int off[181];
    int a = blockIdx.x, t = threadIdx.x;

    for (int r = 0; r < 180; r++) hist[t][r] = 0;
    const unsigned char* segrow = g_seg + a * HW + t * 128;   // thread t owns row y=t
    for (int x = 0; x < 128; x++) hist[t][segrow[x]]++;
    __syncthreads();

    // per-bin exclusive prefix over chunks; totals into off[r]
    for (int r = t; r < 180; r += 128) {
        int run = 0;
        for (int q = 0; q < 128; q++) {
            int tmp = hist[q][r];
            hist[q][r] = (unsigned short)run;
            run += tmp;
        }
        off[r] = run;
    }
    __syncthreads();
    if (t == 0) {
        int run = 0;
        for (int r = 0; r < 180; r++) { int tot = off[r]; off[r] = run; run += tot; }
        off[180] = run;   // 16384
    }
    __syncthreads();

    unsigned short* myh = hist[t];
    for (int x = 0; x < 128; x++) {
        int r = segrow[x];
        int pos = off[r] + myh[r];
        myh[r]++;
        g_csr_idx[a * HW + pos] = (unsigned short)(t * 128 + x);
    }
    for (int i = t; i < 181; i += 128) g_csr_ptr[a * 181 + i] = off[i];
}

// ---------------- weight transpose + tf32 round: w[co][k] -> wt[k][co] ----------------
__global__ void wt_kernel(const float* __restrict__ w, float* __restrict__ wt) {
    int e = blockIdx.x * 256 + threadIdx.x;
    if (e < 1152 * 128) {
        int co = e & 127;
        int k  = e >> 7;
        wt[e] = to_tf32(w[co * 1152 + k]);
    }
}

// ---------------- conv1: 1x1 conv + BN + ReLU, GEMM 128co x 64px, K=256 ----------------
__global__ __launch_bounds__(256) void conv1_kernel(
    const float* __restrict__ x, const float* __restrict__ w,
    const float* __restrict__ b, const float* __restrict__ g,
    const float* __restrict__ be, const float* __restrict__ m,
    const float* __restrict__ v)
{
    __shared__ float As[8][128];
    __shared__ float Bs[8][64];
    __shared__ float sS[128], tS[128];
    int t = threadIdx.x;
    if (t < 128) {
        float sc = g[t] * rsqrtf(v[t] + 1e-5f);
        sS[t] = sc;
        tS[t] = (b[t] - m[t]) * sc + be[t];
    }
    int col0 = blockIdx.x * 64;
    int n  = col0 >> 14;
    int p0 = col0 & (HW - 1);

    float acc[8][4];
#pragma unroll
    for (int i = 0; i < 8; i++)
#pragma unroll
        for (int j = 0; j < 4; j++) acc[i][j] = 0.f;

    int a_kk = t & 7;
    int b_cc = t & 63;
    int b_kb = t >> 6;

    for (int k0 = 0; k0 < CI1; k0 += 8) {
        __syncthreads();
#pragma unroll
        for (int i = 0; i < 4; i++) {
            int co = (t >> 3) + 32 * i;
            As[a_kk][co] = w[co * CI1 + k0 + a_kk];
        }
#pragma unroll
        for (int i = 0; i < 2; i++) {
            int kk = b_kb + 4 * i;
            Bs[kk][b_cc] = x[(size_t)(n * CI1 + k0 + kk) * HW + p0 + b_cc];
        }
        __syncthreads();
#pragma unroll
        for (int kk = 0; kk < 8; kk++) {
            float av[8], bv[4];
#pragma unroll
            for (int i = 0; i < 8; i++) av[i] = As[kk][(t & 15) + 16 * i];
#pragma unroll
            for (int j = 0; j < 4; j++) bv[j] = Bs[kk][(t >> 4) + 16 * j];
#pragma unroll
            for (int i = 0; i < 8; i++)
#pragma unroll
                for (int j = 0; j < 4; j++) acc[i][j] += av[i] * bv[j];
        }
    }
#pragma unroll
    for (int i = 0; i < 8; i++) {
        int co = (t & 15) + 16 * i;
        float sc = sS[co], tt = tS[co];
#pragma unroll
        for (int j = 0; j < 4; j++) {
            int p = p0 + (t >> 4) + 16 * j;
            float yv = fmaxf(acc[i][j] * sc + tt, 0.f);
            g_ft[(size_t)p * NC + n * DIM + co] = __float2half_rn(yv);
        }
    }
}

// ---------------- DHT gather: block (a, n); warp = pixel-balanced bin range ----------------
// thread = 4 channels (8B loads); branch-free unrolled register sums; no smem accumulator.
__global__ __launch_bounds__(128) void dhtg_kernel() {
    __shared__ unsigned short idxS[HW];
    __shared__ int ptrS[181];
    int a = blockIdx.x, n = blockIdx.y, t = threadIdx.x;

    {
        const int4* gs = (const int4*)(g_csr_idx + a * HW);
        int4* ss = (int4*)idxS;
#pragma unroll
        for (int i = 0; i < 16; i++) ss[t + 128 * i] = gs[t + 128 * i];
        for (int i = t; i < 181; i += 128) ptrS[i] = g_csr_ptr[a * 181 + i];
    }
    __syncthreads();

    int w = t >> 5, lane = t & 31;
    // warp w handles bins whose start offset lies in [w*4096, (w+1)*4096)
    int b0 = 0;
    while (b0 < 180 && ptrS[b0] < w * 4096) b0++;
    int b1;
    if (w == 3) b1 = 180;
    else { b1 = 0; while (b1 < 180 && ptrS[b1] < (w + 1) * 4096) b1++; }

    const __half* fbase = g_ft + n * DIM + (lane << 2);

    for (int r = b0; r < b1; r++) {
        int s = ptrS[r], e = ptrS[r + 1];
        float a0 = 0.f, a1 = 0.f, a2 = 0.f, a3 = 0.f;
        float c0 = 0.f, c1 = 0.f, c2 = 0.f, c3 = 0.f;
        int i = s;
        for (; i + 4 <= e; i += 4) {
            int p0 = idxS[i], p1 = idxS[i + 1], p2 = idxS[i + 2], p3 = idxS[i + 3];
            uint2 u0 = *(const uint2*)(fbase + (size_t)p0 * NC);
            uint2 u1 = *(const uint2*)(fbase + (size_t)p1 * NC);
            uint2 u2 = *(const uint2*)(fbase + (size_t)p2 * NC);
            uint2 u3 = *(const uint2*)(fbase + (size_t)p3 * NC);
            float2 f;
            f = __half22float2(*(__half2*)&u0.x); a0 += f.x; a1 += f.y;
            f = __half22float2(*(__half2*)&u0.y); a2 += f.x; a3 += f.y;
            f = __half22float2(*(__half2*)&u1.x); c0 += f.x; c1 += f.y;
            f = __half22float2(*(__half2*)&u1.y); c2 += f.x; c3 += f.y;
            f = __half22float2(*(__half2*)&u2.x); a0 += f.x; a1 += f.y;
            f = __half22float2(*(__half2*)&u2.y); a2 += f.x; a3 += f.y;
            f = __half22float2(*(__half2*)&u3.x); c0 += f.x; c1 += f.y;
            f = __half22float2(*(__half2*)&u3.y); c2 += f.x; c3 += f.y;
        }
        for (; i < e; i++) {
            int p = idxS[i];
            uint2 u = *(const uint2*)(fbase + (size_t)p * NC);
            float2 f;
            f = __half22float2(*(__half2*)&u.x); a0 += f.x; a1 += f.y;
            f = __half22float2(*(__half2*)&u.y); a2 += f.x; a3 += f.y;
        }
        a0 += c0; a1 += c1; a2 += c2; a3 += c3;
        float* dst = g_acc + ((size_t)(n * DIM + (lane << 2)) * 180 + a) * 180 + r;
        dst[0]          = a0;
        dst[AR]         = a1;
        dst[2 * AR]     = a2;
        dst[3 * (size_t)AR] = a3;
    }
}

// ---------------- conv3x3 + BN + ReLU: tf32 mma.sync implicit GEMM (R3-proven) ----------------
#define WS_F   (9 * 8 * 136)
#define BS_F   (8 * 312)
#define C3_SMEM ((WS_F + BS_F + 256) * 4)

__global__ __launch_bounds__(256) void conv3_kernel(
    const float* __restrict__ src, const float* __restrict__ wt,
    const float* __restrict__ b,  const float* __restrict__ g,
    const float* __restrict__ be, const float* __restrict__ m,
    const float* __restrict__ v,  float* __restrict__ dst)
{
    extern __shared__ float dyn[];
    float* Ws  = dyn;                 // [tap*1088 + ci*136 + co]
    float* BsS = dyn + WS_F;          // [ci*312 + ar*104 + rr]
    float* sS  = dyn + WS_F + BS_F;
    float* tS  = sS + 128;

    int t  = threadIdx.x;
    int r0 = blockIdx.x * 84;
    int a  = blockIdx.y;
    int n  = blockIdx.z;
    if (t < 128) {
        float sc = g[t] * rsqrtf(v[t] + 1e-5f);
        sS[t] = sc;
        tS[t] = (b[t] - m[t]) * sc + be[t];
    }

    int lane = t & 31, warp = t >> 5;
    int grp = lane >> 2, q4 = lane & 3;
    int co_base = warp * 16;

    float acc[12][4];
#pragma unroll
    for (int j = 0; j < 12; j++)
#pragma unroll
        for (int i = 0; i < 4; i++) acc[j][i] = 0.f;

    const float* srcn = src + (size_t)n * DIM * AR;

#pragma unroll 1
    for (int c0 = 0; c0 < DIM; c0 += 8) {
        __syncthreads();
        for (int e = t; e < 9 * 8 * 128; e += 256) {
            int tap = e >> 10;
            int ci  = (e >> 7) & 7;
            int co  = e & 127;
            Ws[tap * 1088 + ci * 136 + co] = wt[((size_t)(c0 + ci) * 9 + tap) * 128 + co];
        }
        for (int e = t; e < 8 * 3 * 98; e += 256) {
            int ci  = e / 294;
            int rem = e - ci * 294;
            int ar  = rem / 98;
            int qq  = rem - ar * 98;
            int as  = a + ar - 1;
            int rs  = r0 - 1 + qq;
            float val = 0.f;
            if ((unsigned)as < 180u && (unsigned)rs < 180u)
                val = srcn[((size_t)(c0 + ci) * 180 + as) * 180 + rs];
            BsS[ci * 312 + ar * 104 + qq] = to_tf32(val);
        }
        __syncthreads();

#pragma unroll
        for (int tap = 0; tap < 9; tap++) {
            int ky = tap / 3, kx = tap - 3 * (tap / 3);
            const float* wA = Ws + tap * 1088;
            unsigned av0 = __float_as_uint(wA[q4 * 136 + co_base + grp]);
            unsigned av1 = __float_as_uint(wA[q4 * 136 + co_base + grp + 8]);
            unsigned av2 = __float_as_uint(wA[(q4 + 4) * 136 + co_base + grp]);
            unsigned av3 = __float_as_uint(wA[(q4 + 4) * 136 + co_base + grp + 8]);
            const float* bB = BsS + ky * 104 + kx + grp;
#pragma unroll
            for (int jn = 0; jn < 12; jn++) {
                unsigned bv0 = __float_as_uint(bB[q4 * 312 + jn * 8]);
                unsigned bv1 = __float_as_uint(bB[(q4 + 4) * 312 + jn * 8]);
                asm volatile(
                    "mma.sync.aligned.m16n8k8.row.col.f32.tf32.tf32.f32 "
                    "{%0,%1,%2,%3}, {%4,%5,%6,%7}, {%8,%9}, {%0,%1,%2,%3};"
                    : "+f"(acc[jn][0]), "+f"(acc[jn][1]),
                      "+f"(acc[jn][2]), "+f"(acc[jn][3])
                    : "r"(av0), "r"(av1), "r"(av2), "r"(av3),
                      "r"(bv0), "r"(bv1));
            }
        }
    }

    int co0 = co_base + grp;
    int co1 = co0 + 8;
    float sc0 = sS[co0], tt0 = tS[co0];
    float sc1 = sS[co1], tt1 = tS[co1];
    float* d0 = dst + ((size_t)(n * DIM + co0) * 180 + a) * 180 + r0 + q4 * 2;
    float* d1 = dst + ((size_t)(n * DIM + co1) * 180 + a) * 180 + r0 + q4 * 2;
#pragma unroll
    for (int jn = 0; jn < 12; jn++) {
        float2 o0, o1;
        o0.x = fmaxf(acc[jn][0] * sc0 + tt0, 0.f);
        o0.y = fmaxf(acc[jn][1] * sc0 + tt0, 0.f);
        o1.x = fmaxf(acc[jn][2] * sc1 + tt1, 0.f);
        o1.y = fmaxf(acc[jn][3] * sc1 + tt1, 0.f);
        *(float2*)(d0 + jn * 8) = o0;
        *(float2*)(d1 + jn * 8) = o1;
    }
}

// ---------------- launch ----------------
extern "C" void kernel_launch(void* const* d_in, const int* in_sizes, int n_in,
                              void* d_out, int out_size) {
    const float* x   = (const float*)d_in[0];
    const float* w1  = (const float*)d_in[1];
    const float* b1  = (const float*)d_in[2];
    const float* g1  = (const float*)d_in[3];
    const float* be1 = (const float*)d_in[4];
    const float* m1  = (const float*)d_in[5];
    const float* v1  = (const float*)d_in[6];
    const float* w2  = (const float*)d_in[7];
    const float* b2  = (const float*)d_in[8];
    const float* g2  = (const float*)d_in[9];
    const float* be2 = (const float*)d_in[10];
    const float* m2  = (const float*)d_in[11];
    const float* v2  = (const float*)d_in[12];
    const float* w3  = (const float*)d_in[13];
    const float* b3  = (const float*)d_in[14];
    const float* g3  = (const float*)d_in[15];
    const float* be3 = (const float*)d_in[16];
    const float* m3  = (const float*)d_in[17];
    const float* v3  = (const float*)d_in[18];
    float* out = (float*)d_out;

    void *p_w2t, *p_w3t, *p_acc, *p_y2;
    cudaGetSymbolAddress(&p_w2t, g_w2t);
    cudaGetSymbolAddress(&p_w3t, g_w3t);
    cudaGetSymbolAddress(&p_acc, g_acc);
    cudaGetSymbolAddress(&p_y2,  g_y2);

    cudaFuncSetAttribute(conv3_kernel, cudaFuncAttributeMaxDynamicSharedMemorySize, C3_SMEM);

    // order: dht at my-launch index 3 (where ncu capture landed in R2/R3)
    seg_kernel<<<dim3(A_ANG, HW / 256), 256>>>();
    conv1_kernel<<<(Nn * HW) / 64, 256>>>(x, w1, b1, g1, be1, m1, v1);
    csr_kernel<<<A_ANG, 128>>>();
    dhtg_kernel<<<dim3(A_ANG, Nn), 128>>>();
    wt_kernel<<<(1152 * 128 + 255) / 256, 256>>>(w2, (float*)p_w2t);
    wt_kernel<<<(1152 * 128 + 255) / 256, 256>>>(w3, (float*)p_w3t);
    conv3_kernel<<<dim3(2, A_ANG, Nn), 256, C3_SMEM>>>((const float*)p_acc, (const float*)p_w2t,
                                                       b2, g2, be2, m2, v2, (float*)p_y2);
    conv3_kernel<<<dim3(2, A_ANG, Nn), 256, C3_SMEM>>>((const float*)p_y2, (const float*)p_w3t,
                                                       b3, g3, be3, m3, v3, out);
}

// round 6
// speedup vs baseline: 5.4442x; 1.1989x over previous
#include <cuda_runtime.h>
#include <cuda_fp16.h>
#include <cuda_bf16.h>
#include <math.h>
#include <stdint.h>

#define A_ANG 180
#define R_RHO 180
#define AR    32400
#define Hh    128
#define Ww    128
#define HW    16384
#define Nn    8
#define CI1   256
#define DIM   128
#define NC    1024   /* Nn*DIM */

// ---------------- static device scratch ----------------
__device__ unsigned char  g_seg[A_ANG * HW];
__device__ __half         g_ft[(size_t)HW * NC];           // conv1 out, [pixel][n*128+c] fp16
__device__ float          g_acc[(size_t)Nn * DIM * AR];    // DHT out, NCHW [n][c][a][r]
__device__ float          g_y2 [(size_t)Nn * DIM * AR];    // conv2 out
__device__ __half2        g_w2h[9 * 64 * 128];             // weights [tap][ci2][co], half2 over ci pair
__device__ __half2        g_w3h[9 * 64 * 128];
__device__ unsigned short g_csr_idx[A_ANG * HW];           // pixel lists per (angle, bin)
__device__ int            g_csr_ptr[A_ANG * 181];          // row pointers per angle

// ---------------- seg table: fp64, bit-matches numpy binning ----------------
__global__ void seg_kernel() {
    int a = blockIdx.x;
    int p = blockIdx.y * 256 + threadIdx.x;
    double irho = (double)((int)(sqrt((double)(Hh * Hh + Ww * Ww)) + 1.0)) / (double)(R_RHO - 1);
    double theta = (double)a * (3.141592653589793 / (double)A_ANG);
    double tc = cos(theta) / irho;
    double ts = sin(theta) / irho;
    int y = p >> 7, x = p & (Ww - 1);
    double val = __dadd_rn(__dmul_rn(tc, (double)(x - Ww / 2)),
                           __dmul_rn(ts, (double)(y - Hh / 2)));
    long long r = (long long)rint(val) + R_RHO / 2;
    if (r < 0) r = 0;
    if (r > R_RHO - 1) r = R_RHO - 1;
    g_seg[a * HW + p] = (unsigned char)r;
}

// ---------------- CSR build: per angle, deterministic two-pass rank fill ----------------
__global__ __launch_bounds__(128) void csr_kernel() {
    __shared__ unsigned short hist[128][180];
    __shared__ int off[181];
    int a = blockIdx.x, t = threadIdx.x;

    for (int r = 0; r < 180; r++) hist[t][r] = 0;
    const unsigned char* segrow = g_seg + a * HW + t * 128;
    for (int x = 0; x < 128; x++) hist[t][segrow[x]]++;
    __syncthreads();

    for (int r = t; r < 180; r += 128) {
        int run = 0;
        for (int q = 0; q < 128; q++) {
            int tmp = hist[q][r];
            hist[q][r] = (unsigned short)run;
            run += tmp;
        }
        off[r] = run;
    }
    __syncthreads();
    if (t == 0) {
        int run = 0;
        for (int r = 0; r < 180; r++) { int tot = off[r]; off[r] = run; run += tot; }
        off[180] = run;
    }
    __syncthreads();

    unsigned short* myh = hist[t];
    for (int x = 0; x < 128; x++) {
        int r = segrow[x];
        int pos = off[r] + myh[r];
        myh[r]++;
        g_csr_idx[a * HW + pos] = (unsigned short)(t * 128 + x);
    }
    for (int i = t; i < 181; i += 128) g_csr_ptr[a * 181 + i] = off[i];
}

// ---------------- weight prep: w[co][ci][tap] -> half2 [tap][ci2][co] ----------------
__global__ void wpreph_kernel(const float* __restrict__ w, __half2* __restrict__ wh) {
    int e = blockIdx.x * 256 + threadIdx.x;
    if (e < 9 * 64 * 128) {
        int tap = e >> 13;              // e / (64*128)
        int ci2 = (e >> 7) & 63;
        int co  = e & 127;
        float lo = w[co * 1152 + (2 * ci2) * 9 + tap];
        float hi = w[co * 1152 + (2 * ci2 + 1) * 9 + tap];
        wh[e] = __floats2half2_rn(lo, hi);
    }
}

// ---------------- conv1: 1x1 conv + BN + ReLU, GEMM 128co x 64px, K=256 ----------------
__global__ __launch_bounds__(256) void conv1_kernel(
    const float* __restrict__ x, const float* __restrict__ w,
    const float* __restrict__ b, const float* __restrict__ g,
    const float* __restrict__ be, const float* __restrict__ m,
    const float* __restrict__ v)
{
    __shared__ float As[8][128];
    __shared__ float Bs[8][64];
    __shared__ float sS[128], tS[128];
    int t = threadIdx.x;
    if (t < 128) {
        float sc = g[t] * rsqrtf(v[t] + 1e-5f);
        sS[t] = sc;
        tS[t] = (b[t] - m[t]) * sc + be[t];
    }
    int col0 = blockIdx.x * 64;
    int n  = col0 >> 14;
    int p0 = col0 & (HW - 1);

    float acc[8][4];
#pragma unroll
    for (int i = 0; i < 8; i++)
#pragma unroll
        for (int j = 0; j < 4; j++) acc[i][j] = 0.f;

    int a_kk = t & 7;
    int b_cc = t & 63;
    int b_kb = t >> 6;

    for (int k0 = 0; k0 < CI1; k0 += 8) {
        __syncthreads();
#pragma unroll
        for (int i = 0; i < 4; i++) {
            int co = (t >> 3) + 32 * i;
            As[a_kk][co] = w[co * CI1 + k0 + a_kk];
        }
#pragma unroll
        for (int i = 0; i < 2; i++) {
            int kk = b_kb + 4 * i;
            Bs[kk][b_cc] = x[(size_t)(n * CI1 + k0 + kk) * HW + p0 + b_cc];
        }
        __syncthreads();
#pragma unroll
        for (int kk = 0; kk < 8; kk++) {
            float av[8], bv[4];
#pragma unroll
            for (int i = 0; i < 8; i++) av[i] = As[kk][(t & 15) + 16 * i];
#pragma unroll
            for (int j = 0; j < 4; j++) bv[j] = Bs[kk][(t >> 4) + 16 * j];
#pragma unroll
            for (int i = 0; i < 8; i++)
#pragma unroll
                for (int j = 0; j < 4; j++) acc[i][j] += av[i] * bv[j];
        }
    }
#pragma unroll
    for (int i = 0; i < 8; i++) {
        int co = (t & 15) + 16 * i;
        float sc = sS[co], tt = tS[co];
#pragma unroll
        for (int j = 0; j < 4; j++) {
            int p = p0 + (t >> 4) + 16 * j;
            float yv = fmaxf(acc[i][j] * sc + tt, 0.f);
            g_ft[(size_t)p * NC + n * DIM + co] = __float2half_rn(yv);
        }
    }
}

// ---------------- DHT gather: block (a, n); warp = pixel-balanced bin range ----------------
__global__ __launch_bounds__(128) void dhtg_kernel() {
    __shared__ unsigned short idxS[HW];
    __shared__ int ptrS[181];
    int a = blockIdx.x, n = blockIdx.y, t = threadIdx.x;

    {
        const int4* gs = (const int4*)(g_csr_idx + a * HW);
        int4* ss = (int4*)idxS;
#pragma unroll
        for (int i = 0; i < 16; i++) ss[t + 128 * i] = gs[t + 128 * i];
        for (int i = t; i < 181; i += 128) ptrS[i] = g_csr_ptr[a * 181 + i];
    }
    __syncthreads();

    int w = t >> 5, lane = t & 31;
    int b0 = 0;
    while (b0 < 180 && ptrS[b0] < w * 4096) b0++;
    int b1;
    if (w == 3) b1 = 180;
    else { b1 = 0; while (b1 < 180 && ptrS[b1] < (w + 1) * 4096) b1++; }

    const __half* fbase = g_ft + n * DIM + (lane << 2);

    for (int r = b0; r < b1; r++) {
        int s = ptrS[r], e = ptrS[r + 1];
        float a0 = 0.f, a1 = 0.f, a2 = 0.f, a3 = 0.f;
        float c0 = 0.f, c1 = 0.f, c2 = 0.f, c3 = 0.f;
        int i = s;
        for (; i + 4 <= e; i += 4) {
            int p0 = idxS[i], p1 = idxS[i + 1], p2 = idxS[i + 2], p3 = idxS[i + 3];
            uint2 u0 = *(const uint2*)(fbase + (size_t)p0 * NC);
            uint2 u1 = *(const uint2*)(fbase + (size_t)p1 * NC);
            uint2 u2 = *(const uint2*)(fbase + (size_t)p2 * NC);
            uint2 u3 = *(const uint2*)(fbase + (size_t)p3 * NC);
            float2 f;
            f = __half22float2(*(__half2*)&u0.x); a0 += f.x; a1 += f.y;
            f = __half22float2(*(__half2*)&u0.y); a2 += f.x; a3 += f.y;
            f = __half22float2(*(__half2*)&u1.x); c0 += f.x; c1 += f.y;
            f = __half22float2(*(__half2*)&u1.y); c2 += f.x; c3 += f.y;
            f = __half22float2(*(__half2*)&u2.x); a0 += f.x; a1 += f.y;
            f = __half22float2(*(__half2*)&u2.y); a2 += f.x; a3 += f.y;
            f = __half22float2(*(__half2*)&u3.x); c0 += f.x; c1 += f.y;
            f = __half22float2(*(__half2*)&u3.y); c2 += f.x; c3 += f.y;
        }
        for (; i < e; i++) {
            int p = idxS[i];
            uint2 u = *(const uint2*)(fbase + (size_t)p * NC);
            float2 f;
            f = __half22float2(*(__half2*)&u.x); a0 += f.x; a1 += f.y;
            f = __half22float2(*(__half2*)&u.y); a2 += f.x; a3 += f.y;
        }
        a0 += c0; a1 += c1; a2 += c2; a3 += c3;
        float* dst = g_acc + ((size_t)(n * DIM + (lane << 2)) * 180 + a) * 180 + r;
        dst[0]              = a0;
        dst[AR]             = a1;
        dst[2 * AR]         = a2;
        dst[3 * (size_t)AR] = a3;
    }
}

// ---------------- conv3x3 + BN + ReLU: fp16 mma.sync m16n8k16 implicit GEMM ----------------
// tile: 128 co x 96 cols, K = 1152 in ci-chunks of 16 (8 chunks).
// smem (half2 units): Wh2[tap s1088][ci2 s136][co], Bh2[ci2 s312][ar s104][q 0..97]
#define WH2_N   (9 * 8 * 136)      /* 9792 half2 = 39168 B */
#define BH2_N   (8 * 312)          /* 2496 half2 =  9984 B */
#define C3_SMEM (WH2_N * 4 + BH2_N * 4 + 256 * 4)

__global__ __launch_bounds__(256) void conv3h_kernel(
    const float* __restrict__ src, const __half2* __restrict__ wh,
    const float* __restrict__ b,  const float* __restrict__ g,
    const float* __restrict__ be, const float* __restrict__ m,
    const float* __restrict__ v,  float* __restrict__ dst)
{
    extern __shared__ __align__(16) char smraw[];
    __half2* Wh2 = (__half2*)smraw;
    __half2* Bh2 = (__half2*)(smraw + WH2_N * 4);
    float*   sS  = (float*)(smraw + WH2_N * 4 + BH2_N * 4);
    float*   tS  = sS + 128;

    int t  = threadIdx.x;
    int r0 = blockIdx.x * 84;         // 0 or 84 (12-col overlap, identical values)
    int a  = blockIdx.y;
    int n  = blockIdx.z;
    if (t < 128) {
        float sc = g[t] * rsqrtf(v[t] + 1e-5f);
        sS[t] = sc;
        tS[t] = (b[t] - m[t]) * sc + be[t];
    }

    int lane = t & 31, warp = t >> 5;
    int grp = lane >> 2, q4 = lane & 3;
    int co_base = warp * 16;

    float acc[12][4];
#pragma unroll
    for (int j = 0; j < 12; j++)
#pragma unroll
        for (int i = 0; i < 4; i++) acc[j][i] = 0.f;

    const float* srcn = src + (size_t)n * DIM * AR;

#pragma unroll 1
    for (int c0 = 0; c0 < DIM; c0 += 16) {
        int ci2g = c0 >> 1;   // global ci2 base
        __syncthreads();
        // stage weights: Wh2[tap][ci2 0..7][co] <- wh[(tap*64 + ci2g+ci2)*128 + co]
        for (int e = t; e < 9 * 8 * 128; e += 256) {
            int tap = e >> 10;
            int ci2 = (e >> 7) & 7;
            int co  = e & 127;
            Wh2[tap * 1088 + ci2 * 136 + co] = wh[((size_t)tap * 64 + ci2g + ci2) * 128 + co];
        }
        // stage input: ci 0..15, rows a-1..a+1, q 0..97 (r = r0-1+q), fp32 -> half
        __half* Bh = (__half*)Bh2;
        for (int e = t; e < 16 * 3 * 98; e += 256) {
            int ci  = e / 294;
            int rem = e - ci * 294;
            int ar  = rem / 98;
            int qq  = rem - ar * 98;
            int as  = a + ar - 1;
            int rs  = r0 - 1 + qq;
            float val = 0.f;
            if ((unsigned)as < 180u && (unsigned)rs < 180u)
                val = srcn[((size_t)(c0 + ci) * 180 + as) * 180 + rs];
            Bh[(ci >> 1) * 624 + ar * 208 + qq * 2 + (ci & 1)] = __float2half_rn(val);
        }
        __syncthreads();

#pragma unroll
        for (int tap = 0; tap < 9; tap++) {
            int ky = tap / 3, kx = tap - 3 * (tap / 3);
            const __half2* wA = Wh2 + tap * 1088;
            unsigned a0 = *(const unsigned*)(wA + q4 * 136 + co_base + grp);
            unsigned a1 = *(const unsigned*)(wA + q4 * 136 + co_base + grp + 8);
            unsigned a2 = *(const unsigned*)(wA + (q4 + 4) * 136 + co_base + grp);
            unsigned a3 = *(const unsigned*)(wA + (q4 + 4) * 136 + co_base + grp + 8);
            const __half2* bB = Bh2 + ky * 104 + kx + grp;
#pragma unroll
            for (int jn = 0; jn < 12; jn++) {
                unsigned b0 = *(const unsigned*)(bB + q4 * 312 + jn * 8);
                unsigned b1 = *(const unsigned*)(bB + (q4 + 4) * 312 + jn * 8);
                asm volatile(
                    "mma.sync.aligned.m16n8k16.row.col.f32.f16.f16.f32 "
                    "{%0,%1,%2,%3}, {%4,%5,%6,%7}, {%8,%9}, {%0,%1,%2,%3};"
                    : "+f"(acc[jn][0]), "+f"(acc[jn][1]),
                      "+f"(acc[jn][2]), "+f"(acc[jn][3])
                    : "r"(a0), "r"(a1), "r"(a2), "r"(a3),
                      "r"(b0), "r"(b1));
            }
        }
    }

    int co0 = co_base + grp;
    int co1 = co0 + 8;
    float sc0 = sS[co0], tt0 = tS[co0];
    float sc1 = sS[co1], tt1 = tS[co1];
    float* d0 = dst + ((size_t)(n * DIM + co0) * 180 + a) * 180 + r0 + q4 * 2;
    float* d1 = dst + ((size_t)(n * DIM + co1) * 180 + a) * 180 + r0 + q4 * 2;
#pragma unroll
    for (int jn = 0; jn < 12; jn++) {
        float2 o0, o1;
        o0.x = fmaxf(acc[jn][0] * sc0 + tt0, 0.f);
        o0.y = fmaxf(acc[jn][1] * sc0 + tt0, 0.f);
        o1.x = fmaxf(acc[jn][2] * sc1 + tt1, 0.f);
        o1.y = fmaxf(acc[jn][3] * sc1 + tt1, 0.f);
        *(float2*)(d0 + jn * 8) = o0;
        *(float2*)(d1 + jn * 8) = o1;
    }
}

// ---------------- launch ----------------
extern "C" void kernel_launch(void* const* d_in, const int* in_sizes, int n_in,
                              void* d_out, int out_size) {
    const float* x   = (const float*)d_in[0];
    const float* w1  = (const float*)d_in[1];
    const float* b1  = (const float*)d_in[2];
    const float* g1  = (const float*)d_in[3];
    const float* be1 = (const float*)d_in[4];
    const float* m1  = (const float*)d_in[5];
    const float* v1  = (const float*)d_in[6];
    const float* w2  = (const float*)d_in[7];
    const float* b2  = (const float*)d_in[8];
    const float* g2  = (const float*)d_in[9];
    const float* be2 = (const float*)d_in[10];
    const float* m2  = (const float*)d_in[11];
    const float* v2  = (const float*)d_in[12];
    const float* w3  = (const float*)d_in[13];
    const float* b3  = (const float*)d_in[14];
    const float* g3  = (const float*)d_in[15];
    const float* be3 = (const float*)d_in[16];
    const float* m3  = (const float*)d_in[17];
    const float* v3  = (const float*)d_in[18];
    float* out = (float*)d_out;

    void *p_w2h, *p_w3h, *p_acc, *p_y2;
    cudaGetSymbolAddress(&p_w2h, g_w2h);
    cudaGetSymbolAddress(&p_w3h, g_w3h);
    cudaGetSymbolAddress(&p_acc, g_acc);
    cudaGetSymbolAddress(&p_y2,  g_y2);

    cudaFuncSetAttribute(conv3h_kernel, cudaFuncAttributeMaxDynamicSharedMemorySize, C3_SMEM);

    seg_kernel<<<dim3(A_ANG, HW / 256), 256>>>();
    conv1_kernel<<<(Nn * HW) / 64, 256>>>(x, w1, b1, g1, be1, m1, v1);
    csr_kernel<<<A_ANG, 128>>>();
    dhtg_kernel<<<dim3(A_ANG, Nn), 128>>>();
    wpreph_kernel<<<(9 * 64 * 128 + 255) / 256, 256>>>(w2, (__half2*)p_w2h);
    wpreph_kernel<<<(9 * 64 * 128 + 255) / 256, 256>>>(w3, (__half2*)p_w3h);
    conv3h_kernel<<<dim3(2, A_ANG, Nn), 256, C3_SMEM>>>(
        (const float*)p_acc, (const __half2*)p_w2h, b2, g2, be2, m2, v2, (float*)p_y2);
    conv3h_kernel<<<dim3(2, A_ANG, Nn), 256, C3_SMEM>>>(
        (const float*)p_y2, (const __half2*)p_w3h, b3, g3, be3, m3, v3, out);
}